// round 1
// baseline (speedup 1.0000x reference)
#include <cuda_runtime.h>

// Problem constants
#define BB 128
#define TT 256
#define CC 384
#define HH 6
#define DD 64
#define NTOK (BB * TT)   // 32768

// Scratch (static device globals — no dynamic allocation allowed)
__device__ float g_q[BB * HH * TT * DD];     // [b][h][t][d]
__device__ float g_k[BB * HH * TT * DD];
__device__ float g_v[BB * HH * TT * DD];
__device__ float g_attn[NTOK * CC];          // [b*T + t][h*D + d]

// ---------------------------------------------------------------------------
// QKV projection GEMM.
//   out[((b*H + h)*T + t)*D + d] = sum_c X[(b*T+t)*C + c] * W[h*C*D + c*D + d]
// Block tile: 64 (tokens) x 64 (=one head's D). grid = (H, NTOK/64)
// ---------------------------------------------------------------------------
__global__ __launch_bounds__(256) void qkv_gemm(
    const float* __restrict__ X, const float* __restrict__ W,
    float* __restrict__ out)
{
    __shared__ __align__(16) float As[16][68];  // [k][m], padded
    __shared__ __align__(16) float Bs[16][64];  // [k][n]

    const int h   = blockIdx.x;
    const int m0  = blockIdx.y * 64;
    const int tid = threadIdx.x;
    const int tm0 = (tid >> 4) * 4;
    const int tn0 = (tid & 15) * 4;

    // loader indices
    const int ar = tid >> 2;           // 0..63 (token row in tile)
    const int ac = (tid & 3) * 4;      // 0,4,8,12 (k offset)
    const int br = tid >> 4;           // 0..15 (k row)
    const int bc = (tid & 15) * 4;     // 0..60 (n col)

    const float* Wh = W + h * (CC * DD);

    float acc[4][4];
#pragma unroll
    for (int i = 0; i < 4; i++)
#pragma unroll
        for (int j = 0; j < 4; j++) acc[i][j] = 0.0f;

    for (int k0 = 0; k0 < CC; k0 += 16) {
        float4 av = *(const float4*)(X + (long)(m0 + ar) * CC + k0 + ac);
        As[ac + 0][ar] = av.x;
        As[ac + 1][ar] = av.y;
        As[ac + 2][ar] = av.z;
        As[ac + 3][ar] = av.w;
        *(float4*)(&Bs[br][bc]) = *(const float4*)(Wh + (k0 + br) * DD + bc);
        __syncthreads();

#pragma unroll
        for (int kk = 0; kk < 16; kk++) {
            const float4 a = *(const float4*)(&As[kk][tm0]);
            const float4 b = *(const float4*)(&Bs[kk][tn0]);
            const float a4[4] = {a.x, a.y, a.z, a.w};
            const float b4[4] = {b.x, b.y, b.z, b.w};
#pragma unroll
            for (int i = 0; i < 4; i++)
#pragma unroll
                for (int j = 0; j < 4; j++) acc[i][j] += a4[i] * b4[j];
        }
        __syncthreads();
    }

#pragma unroll
    for (int i = 0; i < 4; i++) {
        const int m = m0 + tm0 + i;
        const int bb = m >> 8;        // / TT
        const int t  = m & 255;       // % TT
        float4 r = make_float4(acc[i][0], acc[i][1], acc[i][2], acc[i][3]);
        *(float4*)(out + ((long)(bb * HH + h) * TT + t) * DD + tn0) = r;
    }
}

// ---------------------------------------------------------------------------
// Output projection GEMM with bias.
//   out[m*C + n] = sum_k A[m*C + k] * Wp[k*C + n] + bias[n]
// grid = (C/64, NTOK/64)
// ---------------------------------------------------------------------------
__global__ __launch_bounds__(256) void proj_gemm(
    const float* __restrict__ A, const float* __restrict__ Wp,
    const float* __restrict__ bias, float* __restrict__ out)
{
    __shared__ __align__(16) float As[16][68];
    __shared__ __align__(16) float Bs[16][64];

    const int n0  = blockIdx.x * 64;
    const int m0  = blockIdx.y * 64;
    const int tid = threadIdx.x;
    const int tm0 = (tid >> 4) * 4;
    const int tn0 = (tid & 15) * 4;

    const int ar = tid >> 2;
    const int ac = (tid & 3) * 4;
    const int br = tid >> 4;
    const int bc = (tid & 15) * 4;

    float acc[4][4];
#pragma unroll
    for (int i = 0; i < 4; i++)
#pragma unroll
        for (int j = 0; j < 4; j++) acc[i][j] = 0.0f;

    for (int k0 = 0; k0 < CC; k0 += 16) {
        float4 av = *(const float4*)(A + (long)(m0 + ar) * CC + k0 + ac);
        As[ac + 0][ar] = av.x;
        As[ac + 1][ar] = av.y;
        As[ac + 2][ar] = av.z;
        As[ac + 3][ar] = av.w;
        *(float4*)(&Bs[br][bc]) = *(const float4*)(Wp + (long)(k0 + br) * CC + n0 + bc);
        __syncthreads();

#pragma unroll
        for (int kk = 0; kk < 16; kk++) {
            const float4 a = *(const float4*)(&As[kk][tm0]);
            const float4 b = *(const float4*)(&Bs[kk][tn0]);
            const float a4[4] = {a.x, a.y, a.z, a.w};
            const float b4[4] = {b.x, b.y, b.z, b.w};
#pragma unroll
            for (int i = 0; i < 4; i++)
#pragma unroll
                for (int j = 0; j < 4; j++) acc[i][j] += a4[i] * b4[j];
        }
        __syncthreads();
    }

    const float4 bv = *(const float4*)(bias + n0 + tn0);
    const float b4[4] = {bv.x, bv.y, bv.z, bv.w};
#pragma unroll
    for (int i = 0; i < 4; i++) {
        const int m = m0 + tm0 + i;
        float4 r = make_float4(acc[i][0] + b4[0], acc[i][1] + b4[1],
                               acc[i][2] + b4[2], acc[i][3] + b4[3]);
        *(float4*)(out + (long)m * CC + n0 + tn0) = r;
    }
}

// ---------------------------------------------------------------------------
// Causal flash attention over (b, h, 64-row query block).
// grid = (T/64=4, H, B), block = 256 threads.
// smem tiles (stride 68 to keep float4 alignment + avoid bank conflicts):
//   Qs[d][m], Ks[d][j] (k-major for GEMM microkernel), Vs[j][dd], Ps[j][m]
// Each thread owns a 4x4 register tile; row-softmax reduced over the 16
// threads sharing a row quad via shfl (16-lane groups stay inside a warp).
// ---------------------------------------------------------------------------
#define TILE_F (64 * 68)
#define ATTN_SMEM (4 * TILE_F * (int)sizeof(float))

__global__ __launch_bounds__(256) void attn_kernel(
    const float* __restrict__ Q, const float* __restrict__ K,
    const float* __restrict__ V, float* __restrict__ O)
{
    extern __shared__ __align__(16) float sm[];
    float* Qs = sm;                 // [d*68 + m]
    float* Ks = sm + TILE_F;        // [d*68 + j]
    float* Vs = sm + 2 * TILE_F;    // [j*68 + dd]
    float* Ps = sm + 3 * TILE_F;    // [j*68 + m]

    const int qb  = blockIdx.x;
    const int h   = blockIdx.y;
    const int b   = blockIdx.z;
    const int tid = threadIdx.x;
    const int tm0 = (tid >> 4) * 4;   // 4 query rows
    const int tn0 = (tid & 15) * 4;   // 4 key cols / 4 output dims

    const long baseBH = (long)(b * HH + h) * TT;
    const long baseQ  = (baseBH + qb * 64) * DD;

    // Load Q (transpose to d-major)
    for (int idx = tid; idx < 64 * 64; idx += 256) {
        const int t = idx >> 6, d = idx & 63;
        Qs[d * 68 + t] = Q[baseQ + idx];
    }

    float m_i[4], l_i[4], acc[4][4];
#pragma unroll
    for (int i = 0; i < 4; i++) {
        m_i[i] = -1e30f;
        l_i[i] = 0.0f;
#pragma unroll
        for (int j = 0; j < 4; j++) acc[i][j] = 0.0f;
    }
    __syncthreads();

    for (int kb = 0; kb <= qb; kb++) {
        const long baseK = (baseBH + kb * 64) * DD;
        // Load K (transposed) and V (row-major)
        for (int idx = tid; idx < 64 * 64; idx += 256) {
            const int j = idx >> 6, d = idx & 63;
            Ks[d * 68 + j] = K[baseK + idx];
            Vs[j * 68 + d] = V[baseK + idx];
        }
        __syncthreads();

        // S = Q K^T (4x4 per thread)
        float sc[4][4];
#pragma unroll
        for (int i = 0; i < 4; i++)
#pragma unroll
            for (int j = 0; j < 4; j++) sc[i][j] = 0.0f;

#pragma unroll 8
        for (int d = 0; d < 64; d++) {
            const float4 qv = *(const float4*)(Qs + d * 68 + tm0);
            const float4 kv = *(const float4*)(Ks + d * 68 + tn0);
            const float q4[4] = {qv.x, qv.y, qv.z, qv.w};
            const float k4[4] = {kv.x, kv.y, kv.z, kv.w};
#pragma unroll
            for (int i = 0; i < 4; i++)
#pragma unroll
                for (int j = 0; j < 4; j++) sc[i][j] += q4[i] * k4[j];
        }

        const bool diag = (kb == qb);
        const float scale = 0.125f;   // D^-0.5

        // Online softmax per row (reduce over the 16 lanes of the row group)
#pragma unroll
        for (int i = 0; i < 4; i++) {
            float rmax = -1e30f;
#pragma unroll
            for (int j = 0; j < 4; j++) {
                float sv = sc[i][j] * scale;
                if (diag && (tn0 + j) > (tm0 + i)) sv = -1e30f;
                sc[i][j] = sv;
                rmax = fmaxf(rmax, sv);
            }
            rmax = fmaxf(rmax, __shfl_xor_sync(0xffffffffu, rmax, 1));
            rmax = fmaxf(rmax, __shfl_xor_sync(0xffffffffu, rmax, 2));
            rmax = fmaxf(rmax, __shfl_xor_sync(0xffffffffu, rmax, 4));
            rmax = fmaxf(rmax, __shfl_xor_sync(0xffffffffu, rmax, 8));

            const float mnew = fmaxf(m_i[i], rmax);
            const float corr = __expf(m_i[i] - mnew);
            m_i[i] = mnew;

            float ls = 0.0f;
#pragma unroll
            for (int j = 0; j < 4; j++) {
                const float pv = __expf(sc[i][j] - mnew);
                sc[i][j] = pv;
                ls += pv;
            }
            ls += __shfl_xor_sync(0xffffffffu, ls, 1);
            ls += __shfl_xor_sync(0xffffffffu, ls, 2);
            ls += __shfl_xor_sync(0xffffffffu, ls, 4);
            ls += __shfl_xor_sync(0xffffffffu, ls, 8);

            l_i[i] = l_i[i] * corr + ls;
#pragma unroll
            for (int j = 0; j < 4; j++) acc[i][j] *= corr;
        }

        // Store P transposed: Ps[key j][query m]
#pragma unroll
        for (int j = 0; j < 4; j++)
#pragma unroll
            for (int i = 0; i < 4; i++)
                Ps[(tn0 + j) * 68 + tm0 + i] = sc[i][j];
        __syncthreads();

        // O += P V (4 rows x 4 dims per thread)
#pragma unroll 8
        for (int j = 0; j < 64; j++) {
            const float4 pv = *(const float4*)(Ps + j * 68 + tm0);
            const float4 vv = *(const float4*)(Vs + j * 68 + tn0);
            const float p4[4] = {pv.x, pv.y, pv.z, pv.w};
            const float v4[4] = {vv.x, vv.y, vv.z, vv.w};
#pragma unroll
            for (int i = 0; i < 4; i++)
#pragma unroll
                for (int jj = 0; jj < 4; jj++) acc[i][jj] += p4[i] * v4[jj];
        }
        __syncthreads();
    }

    // Write: attn[(b*T + t)*C + h*D + dd]
#pragma unroll
    for (int i = 0; i < 4; i++) {
        const float inv = 1.0f / l_i[i];
        const int t = qb * 64 + tm0 + i;
        float4 r = make_float4(acc[i][0] * inv, acc[i][1] * inv,
                               acc[i][2] * inv, acc[i][3] * inv);
        *(float4*)(O + ((long)(b * TT + t)) * CC + h * DD + tn0) = r;
    }
}

// ---------------------------------------------------------------------------
extern "C" void kernel_launch(void* const* d_in, const int* in_sizes, int n_in,
                              void* d_out, int out_size)
{
    const float* x  = (const float*)d_in[0];
    const float* wq = (const float*)d_in[1];
    const float* wk = (const float*)d_in[2];
    const float* wv = (const float*)d_in[3];
    const float* wp = (const float*)d_in[4];
    const float* bp = (const float*)d_in[5];
    float* out = (float*)d_out;

    float *qp, *kp, *vp, *ap;
    cudaGetSymbolAddress((void**)&qp, g_q);
    cudaGetSymbolAddress((void**)&kp, g_k);
    cudaGetSymbolAddress((void**)&vp, g_v);
    cudaGetSymbolAddress((void**)&ap, g_attn);

    dim3 blk(256);
    dim3 gq(HH, NTOK / 64);
    qkv_gemm<<<gq, blk>>>(x, wq, qp);
    qkv_gemm<<<gq, blk>>>(x, wk, kp);
    qkv_gemm<<<gq, blk>>>(x, wv, vp);

    cudaFuncSetAttribute(attn_kernel,
                         cudaFuncAttributeMaxDynamicSharedMemorySize, ATTN_SMEM);
    attn_kernel<<<dim3(TT / 64, HH, BB), blk, ATTN_SMEM>>>(qp, kp, vp, ap);

    proj_gemm<<<dim3(CC / 64, NTOK / 64), blk>>>(ap, wp, bp, out);
}

// round 2
// speedup vs baseline: 1.0017x; 1.0017x over previous
#include <cuda_runtime.h>

// Problem constants
#define BB 128
#define TT 256
#define CC 384
#define HH 6
#define DD 64
#define NTOK (BB * TT)   // 32768

// Scratch (static device globals — no dynamic allocation allowed)
__device__ float g_q[BB * HH * TT * DD];     // [b][h][t][d]
__device__ float g_k[BB * HH * TT * DD];
__device__ float g_v[BB * HH * TT * DD];
__device__ float g_attn[NTOK * CC];          // [b*T + t][h*D + d]

// ---------------------------------------------------------------------------
// QKV projection GEMM.
//   out[((b*H + h)*T + t)*D + d] = sum_c X[(b*T+t)*C + c] * W[h*C*D + c*D + d]
// Block tile: 64 (tokens) x 64 (=one head's D). grid = (H, NTOK/64)
// ---------------------------------------------------------------------------
__global__ __launch_bounds__(256) void qkv_gemm(
    const float* __restrict__ X, const float* __restrict__ W,
    float* __restrict__ out)
{
    __shared__ __align__(16) float As[16][68];  // [k][m], padded
    __shared__ __align__(16) float Bs[16][64];  // [k][n]

    const int h   = blockIdx.x;
    const int m0  = blockIdx.y * 64;
    const int tid = threadIdx.x;
    const int tm0 = (tid >> 4) * 4;
    const int tn0 = (tid & 15) * 4;

    // loader indices
    const int ar = tid >> 2;           // 0..63 (token row in tile)
    const int ac = (tid & 3) * 4;      // 0,4,8,12 (k offset)
    const int br = tid >> 4;           // 0..15 (k row)
    const int bc = (tid & 15) * 4;     // 0..60 (n col)

    const float* Wh = W + h * (CC * DD);

    float acc[4][4];
#pragma unroll
    for (int i = 0; i < 4; i++)
#pragma unroll
        for (int j = 0; j < 4; j++) acc[i][j] = 0.0f;

    for (int k0 = 0; k0 < CC; k0 += 16) {
        float4 av = *(const float4*)(X + (long)(m0 + ar) * CC + k0 + ac);
        As[ac + 0][ar] = av.x;
        As[ac + 1][ar] = av.y;
        As[ac + 2][ar] = av.z;
        As[ac + 3][ar] = av.w;
        *(float4*)(&Bs[br][bc]) = *(const float4*)(Wh + (k0 + br) * DD + bc);
        __syncthreads();

#pragma unroll
        for (int kk = 0; kk < 16; kk++) {
            const float4 a = *(const float4*)(&As[kk][tm0]);
            const float4 b = *(const float4*)(&Bs[kk][tn0]);
            const float a4[4] = {a.x, a.y, a.z, a.w};
            const float b4[4] = {b.x, b.y, b.z, b.w};
#pragma unroll
            for (int i = 0; i < 4; i++)
#pragma unroll
                for (int j = 0; j < 4; j++) acc[i][j] += a4[i] * b4[j];
        }
        __syncthreads();
    }

#pragma unroll
    for (int i = 0; i < 4; i++) {
        const int m = m0 + tm0 + i;
        const int bb = m >> 8;        // / TT
        const int t  = m & 255;       // % TT
        float4 r = make_float4(acc[i][0], acc[i][1], acc[i][2], acc[i][3]);
        *(float4*)(out + ((long)(bb * HH + h) * TT + t) * DD + tn0) = r;
    }
}

// ---------------------------------------------------------------------------
// Output projection GEMM with bias.
//   out[m*C + n] = sum_k A[m*C + k] * Wp[k*C + n] + bias[n]
// grid = (C/64, NTOK/64)
// ---------------------------------------------------------------------------
__global__ __launch_bounds__(256) void proj_gemm(
    const float* __restrict__ A, const float* __restrict__ Wp,
    const float* __restrict__ bias, float* __restrict__ out)
{
    __shared__ __align__(16) float As[16][68];
    __shared__ __align__(16) float Bs[16][64];

    const int n0  = blockIdx.x * 64;
    const int m0  = blockIdx.y * 64;
    const int tid = threadIdx.x;
    const int tm0 = (tid >> 4) * 4;
    const int tn0 = (tid & 15) * 4;

    const int ar = tid >> 2;
    const int ac = (tid & 3) * 4;
    const int br = tid >> 4;
    const int bc = (tid & 15) * 4;

    float acc[4][4];
#pragma unroll
    for (int i = 0; i < 4; i++)
#pragma unroll
        for (int j = 0; j < 4; j++) acc[i][j] = 0.0f;

    for (int k0 = 0; k0 < CC; k0 += 16) {
        float4 av = *(const float4*)(A + (long)(m0 + ar) * CC + k0 + ac);
        As[ac + 0][ar] = av.x;
        As[ac + 1][ar] = av.y;
        As[ac + 2][ar] = av.z;
        As[ac + 3][ar] = av.w;
        *(float4*)(&Bs[br][bc]) = *(const float4*)(Wp + (long)(k0 + br) * CC + n0 + bc);
        __syncthreads();

#pragma unroll
        for (int kk = 0; kk < 16; kk++) {
            const float4 a = *(const float4*)(&As[kk][tm0]);
            const float4 b = *(const float4*)(&Bs[kk][tn0]);
            const float a4[4] = {a.x, a.y, a.z, a.w};
            const float b4[4] = {b.x, b.y, b.z, b.w};
#pragma unroll
            for (int i = 0; i < 4; i++)
#pragma unroll
                for (int j = 0; j < 4; j++) acc[i][j] += a4[i] * b4[j];
        }
        __syncthreads();
    }

    const float4 bv = *(const float4*)(bias + n0 + tn0);
    const float b4[4] = {bv.x, bv.y, bv.z, bv.w};
#pragma unroll
    for (int i = 0; i < 4; i++) {
        const int m = m0 + tm0 + i;
        float4 r = make_float4(acc[i][0] + b4[0], acc[i][1] + b4[1],
                               acc[i][2] + b4[2], acc[i][3] + b4[3]);
        *(float4*)(out + (long)m * CC + n0 + tn0) = r;
    }
}

// ---------------------------------------------------------------------------
// Causal flash attention over (b, h, 64-row query block).
// grid = (T/64=4, H, B), block = 256 threads.
// smem tiles (stride 68 to keep float4 alignment + avoid bank conflicts):
//   Qs[d][m], Ks[d][j] (k-major for GEMM microkernel), Vs[j][dd], Ps[j][m]
// Each thread owns a 4x4 register tile; row-softmax reduced over the 16
// threads sharing a row quad via shfl (16-lane groups stay inside a warp).
// ---------------------------------------------------------------------------
#define TILE_F (64 * 68)
#define ATTN_SMEM (4 * TILE_F * (int)sizeof(float))

__global__ __launch_bounds__(256) void attn_kernel(
    const float* __restrict__ Q, const float* __restrict__ K,
    const float* __restrict__ V, float* __restrict__ O)
{
    extern __shared__ __align__(16) float sm[];
    float* Qs = sm;                 // [d*68 + m]
    float* Ks = sm + TILE_F;        // [d*68 + j]
    float* Vs = sm + 2 * TILE_F;    // [j*68 + dd]
    float* Ps = sm + 3 * TILE_F;    // [j*68 + m]

    const int qb  = blockIdx.x;
    const int h   = blockIdx.y;
    const int b   = blockIdx.z;
    const int tid = threadIdx.x;
    const int tm0 = (tid >> 4) * 4;   // 4 query rows
    const int tn0 = (tid & 15) * 4;   // 4 key cols / 4 output dims

    const long baseBH = (long)(b * HH + h) * TT;
    const long baseQ  = (baseBH + qb * 64) * DD;

    // Load Q (transpose to d-major)
    for (int idx = tid; idx < 64 * 64; idx += 256) {
        const int t = idx >> 6, d = idx & 63;
        Qs[d * 68 + t] = Q[baseQ + idx];
    }

    float m_i[4], l_i[4], acc[4][4];
#pragma unroll
    for (int i = 0; i < 4; i++) {
        m_i[i] = -1e30f;
        l_i[i] = 0.0f;
#pragma unroll
        for (int j = 0; j < 4; j++) acc[i][j] = 0.0f;
    }
    __syncthreads();

    for (int kb = 0; kb <= qb; kb++) {
        const long baseK = (baseBH + kb * 64) * DD;
        // Load K (transposed) and V (row-major)
        for (int idx = tid; idx < 64 * 64; idx += 256) {
            const int j = idx >> 6, d = idx & 63;
            Ks[d * 68 + j] = K[baseK + idx];
            Vs[j * 68 + d] = V[baseK + idx];
        }
        __syncthreads();

        // S = Q K^T (4x4 per thread)
        float sc[4][4];
#pragma unroll
        for (int i = 0; i < 4; i++)
#pragma unroll
            for (int j = 0; j < 4; j++) sc[i][j] = 0.0f;

#pragma unroll 8
        for (int d = 0; d < 64; d++) {
            const float4 qv = *(const float4*)(Qs + d * 68 + tm0);
            const float4 kv = *(const float4*)(Ks + d * 68 + tn0);
            const float q4[4] = {qv.x, qv.y, qv.z, qv.w};
            const float k4[4] = {kv.x, kv.y, kv.z, kv.w};
#pragma unroll
            for (int i = 0; i < 4; i++)
#pragma unroll
                for (int j = 0; j < 4; j++) sc[i][j] += q4[i] * k4[j];
        }

        const bool diag = (kb == qb);
        const float scale = 0.125f;   // D^-0.5

        // Online softmax per row (reduce over the 16 lanes of the row group)
#pragma unroll
        for (int i = 0; i < 4; i++) {
            float rmax = -1e30f;
#pragma unroll
            for (int j = 0; j < 4; j++) {
                float sv = sc[i][j] * scale;
                if (diag && (tn0 + j) > (tm0 + i)) sv = -1e30f;
                sc[i][j] = sv;
                rmax = fmaxf(rmax, sv);
            }
            rmax = fmaxf(rmax, __shfl_xor_sync(0xffffffffu, rmax, 1));
            rmax = fmaxf(rmax, __shfl_xor_sync(0xffffffffu, rmax, 2));
            rmax = fmaxf(rmax, __shfl_xor_sync(0xffffffffu, rmax, 4));
            rmax = fmaxf(rmax, __shfl_xor_sync(0xffffffffu, rmax, 8));

            const float mnew = fmaxf(m_i[i], rmax);
            const float corr = __expf(m_i[i] - mnew);
            m_i[i] = mnew;

            float ls = 0.0f;
#pragma unroll
            for (int j = 0; j < 4; j++) {
                const float pv = __expf(sc[i][j] - mnew);
                sc[i][j] = pv;
                ls += pv;
            }
            ls += __shfl_xor_sync(0xffffffffu, ls, 1);
            ls += __shfl_xor_sync(0xffffffffu, ls, 2);
            ls += __shfl_xor_sync(0xffffffffu, ls, 4);
            ls += __shfl_xor_sync(0xffffffffu, ls, 8);

            l_i[i] = l_i[i] * corr + ls;
#pragma unroll
            for (int j = 0; j < 4; j++) acc[i][j] *= corr;
        }

        // Store P transposed: Ps[key j][query m]
#pragma unroll
        for (int j = 0; j < 4; j++)
#pragma unroll
            for (int i = 0; i < 4; i++)
                Ps[(tn0 + j) * 68 + tm0 + i] = sc[i][j];
        __syncthreads();

        // O += P V (4 rows x 4 dims per thread)
#pragma unroll 8
        for (int j = 0; j < 64; j++) {
            const float4 pv = *(const float4*)(Ps + j * 68 + tm0);
            const float4 vv = *(const float4*)(Vs + j * 68 + tn0);
            const float p4[4] = {pv.x, pv.y, pv.z, pv.w};
            const float v4[4] = {vv.x, vv.y, vv.z, vv.w};
#pragma unroll
            for (int i = 0; i < 4; i++)
#pragma unroll
                for (int jj = 0; jj < 4; jj++) acc[i][jj] += p4[i] * v4[jj];
        }
        __syncthreads();
    }

    // Write: attn[(b*T + t)*C + h*D + dd]
#pragma unroll
    for (int i = 0; i < 4; i++) {
        const float inv = 1.0f / l_i[i];
        const int t = qb * 64 + tm0 + i;
        float4 r = make_float4(acc[i][0] * inv, acc[i][1] * inv,
                               acc[i][2] * inv, acc[i][3] * inv);
        *(float4*)(O + ((long)(b * TT + t)) * CC + h * DD + tn0) = r;
    }
}

// ---------------------------------------------------------------------------
extern "C" void kernel_launch(void* const* d_in, const int* in_sizes, int n_in,
                              void* d_out, int out_size)
{
    const float* x  = (const float*)d_in[0];
    const float* wq = (const float*)d_in[1];
    const float* wk = (const float*)d_in[2];
    const float* wv = (const float*)d_in[3];
    const float* wp = (const float*)d_in[4];
    const float* bp = (const float*)d_in[5];
    float* out = (float*)d_out;

    float *qp, *kp, *vp, *ap;
    cudaGetSymbolAddress((void**)&qp, g_q);
    cudaGetSymbolAddress((void**)&kp, g_k);
    cudaGetSymbolAddress((void**)&vp, g_v);
    cudaGetSymbolAddress((void**)&ap, g_attn);

    dim3 blk(256);
    dim3 gq(HH, NTOK / 64);
    qkv_gemm<<<gq, blk>>>(x, wq, qp);
    qkv_gemm<<<gq, blk>>>(x, wk, kp);
    qkv_gemm<<<gq, blk>>>(x, wv, vp);

    cudaFuncSetAttribute(attn_kernel,
                         cudaFuncAttributeMaxDynamicSharedMemorySize, ATTN_SMEM);
    attn_kernel<<<dim3(TT / 64, HH, BB), blk, ATTN_SMEM>>>(qp, kp, vp, ap);

    proj_gemm<<<dim3(CC / 64, NTOK / 64), blk>>>(ap, wp, bp, out);
}

// round 4
// speedup vs baseline: 2.1094x; 2.1057x over previous
#include <cuda_runtime.h>
#include <cstdint>

// Problem constants
#define BB 128
#define TT 256
#define CC 384
#define HH 6
#define DD 64
#define NTOK (BB * TT)   // 32768

// Scratch (static device globals — no dynamic allocation allowed)
__device__ float g_q[NTOK * CC];       // [b*T+t][h*64+d]
__device__ float g_k[NTOK * CC];
__device__ float g_v[NTOK * CC];
__device__ float g_attn[NTOK * CC];    // [b*T + t][h*D + d]
__device__ float g_wqT[CC * CC];       // [n=h*64+d][k=c]  K-major
__device__ float g_wkT[CC * CC];
__device__ float g_wvT[CC * CC];
__device__ float g_wpT[CC * CC];       // [n][k]

// ---------------------------------------------------------------------------
__device__ __forceinline__ float tf32r(float x) {
    uint32_t o;
    asm("cvt.rna.tf32.f32 %0, %1;" : "=r"(o) : "f"(x));
    return __uint_as_float(o);
}

__device__ __forceinline__ void mma_tf32(float* c, const uint32_t* a,
                                         const uint32_t* b) {
    asm volatile(
        "mma.sync.aligned.m16n8k8.row.col.f32.tf32.tf32.f32 "
        "{%0,%1,%2,%3}, {%4,%5,%6,%7}, {%8,%9}, {%0,%1,%2,%3};"
        : "+f"(c[0]), "+f"(c[1]), "+f"(c[2]), "+f"(c[3])
        : "r"(a[0]), "r"(a[1]), "r"(a[2]), "r"(a[3]), "r"(b[0]), "r"(b[1]));
}

// ===========================================================================
// Weight transpose: produce K-major B operands.
//   wxT[n=h*64+d][k=c] = wx[h][c][d];  wpT[n][k] = wp[k][n]
// ===========================================================================
__global__ void transpose_w(const float* __restrict__ wq, const float* __restrict__ wk,
                            const float* __restrict__ wv, const float* __restrict__ wp,
                            float* __restrict__ qT, float* __restrict__ kT,
                            float* __restrict__ vT, float* __restrict__ pT)
{
    int idx = blockIdx.x * 256 + threadIdx.x;
    if (idx >= CC * CC) return;
    int n = idx / CC, k = idx - n * CC;
    int h = n >> 6, d = n & 63;
    int src = (h * CC + k) * DD + d;
    qT[idx] = wq[src];
    kT[idx] = wk[src];
    vT[idx] = wv[src];
    pT[idx] = wp[k * CC + n];
}

// ===========================================================================
// Tensor-core (mma.sync tf32) GEMM: C[m][n] = sum_k A[m][k]*Bt[n][k] (+bias)
//   CTA tile 128x128, warp tile 64x32, K-chunk 32, double-buffered SMEM.
//   grid = (NTOK/128, CC/128), block = 256.
// ===========================================================================
#define KTILE 32
#define NCHUNK (CC / KTILE)     // 12
#define SSTR 36                 // smem row stride (floats), conflict-free
#define ASF (128 * SSTR)        // one stage, floats
#define GEMM_SMEM (4 * ASF * (int)sizeof(float))   // A0,A1,B0,B1 = 73728 B

__global__ __launch_bounds__(256) void gemm_mma(
    const float* __restrict__ A, const float* __restrict__ Bt,
    const float* __restrict__ bias, float* __restrict__ Cout)
{
    extern __shared__ __align__(16) float sm[];
    // stages: As = sm + s*ASF ; Bs = sm + 2*ASF + s*ASF
    const int tid = threadIdx.x;
    const int wid = tid >> 5, lane = tid & 31;
    const int gid = lane >> 2, tig = lane & 3;
    const int warp_m = wid & 1;      // 2 x 64 rows
    const int warp_n = wid >> 1;     // 4 x 32 cols
    const int m0 = blockIdx.x * 128;
    const int n0 = blockIdx.y * 128;

    // loader coords: 1024 float4 per operand tile, 4 per thread
    const int lr[4] = { (tid + 0) >> 3, (tid + 256) >> 3,
                        (tid + 512) >> 3, (tid + 768) >> 3 };
    const int lc = (tid & 7) * 4;

    float acc[4][4][4];   // [mtile][ntile][reg]
#pragma unroll
    for (int i = 0; i < 4; i++)
#pragma unroll
        for (int j = 0; j < 4; j++)
#pragma unroll
            for (int r = 0; r < 4; r++) acc[i][j][r] = 0.0f;

    float4 ra[4], rb[4];

    // prologue: load chunk 0
#pragma unroll
    for (int i = 0; i < 4; i++) {
        ra[i] = *(const float4*)(A  + (long)(m0 + lr[i]) * CC + lc);
        rb[i] = *(const float4*)(Bt + (long)(n0 + lr[i]) * CC + lc);
    }
#pragma unroll
    for (int i = 0; i < 4; i++) {
        float* as = sm + 0 * ASF + lr[i] * SSTR + lc;
        float* bs = sm + 2 * ASF + lr[i] * SSTR + lc;
        as[0] = tf32r(ra[i].x); as[1] = tf32r(ra[i].y);
        as[2] = tf32r(ra[i].z); as[3] = tf32r(ra[i].w);
        bs[0] = tf32r(rb[i].x); bs[1] = tf32r(rb[i].y);
        bs[2] = tf32r(rb[i].z); bs[3] = tf32r(rb[i].w);
    }
    __syncthreads();

    for (int c = 0; c < NCHUNK; c++) {
        const int s = c & 1;
        const bool more = (c + 1 < NCHUNK);
        if (more) {
            const int k0 = (c + 1) * KTILE;
#pragma unroll
            for (int i = 0; i < 4; i++) {
                ra[i] = *(const float4*)(A  + (long)(m0 + lr[i]) * CC + k0 + lc);
                rb[i] = *(const float4*)(Bt + (long)(n0 + lr[i]) * CC + k0 + lc);
            }
        }

        const float* As = sm + s * ASF;
        const float* Bs = sm + (2 + s) * ASF;
        const uint32_t* Au = (const uint32_t*)As;
        const uint32_t* Bu = (const uint32_t*)Bs;

#pragma unroll
        for (int ks = 0; ks < 4; ks++) {
            uint32_t af[4][4], bf[4][2];
#pragma unroll
            for (int mt = 0; mt < 4; mt++) {
                const int row = warp_m * 64 + mt * 16 + gid;
                const int col = ks * 8 + tig;
                af[mt][0] = Au[row * SSTR + col];
                af[mt][1] = Au[(row + 8) * SSTR + col];
                af[mt][2] = Au[row * SSTR + col + 4];
                af[mt][3] = Au[(row + 8) * SSTR + col + 4];
            }
#pragma unroll
            for (int nt = 0; nt < 4; nt++) {
                const int row = warp_n * 32 + nt * 8 + gid;
                const int col = ks * 8 + tig;
                bf[nt][0] = Bu[row * SSTR + col];
                bf[nt][1] = Bu[row * SSTR + col + 4];
            }
#pragma unroll
            for (int mt = 0; mt < 4; mt++)
#pragma unroll
                for (int nt = 0; nt < 4; nt++)
                    mma_tf32(acc[mt][nt], af[mt], bf[nt]);
        }

        if (more) {
            const int so = s ^ 1;
#pragma unroll
            for (int i = 0; i < 4; i++) {
                float* as = sm + so * ASF + lr[i] * SSTR + lc;
                float* bs = sm + (2 + so) * ASF + lr[i] * SSTR + lc;
                as[0] = tf32r(ra[i].x); as[1] = tf32r(ra[i].y);
                as[2] = tf32r(ra[i].z); as[3] = tf32r(ra[i].w);
                bs[0] = tf32r(rb[i].x); bs[1] = tf32r(rb[i].y);
                bs[2] = tf32r(rb[i].z); bs[3] = tf32r(rb[i].w);
            }
            __syncthreads();
        }
    }

    // Epilogue: c0,c1 -> (row gid, cols 2*tig,2*tig+1); c2,c3 -> row gid+8
#pragma unroll
    for (int mt = 0; mt < 4; mt++) {
#pragma unroll
        for (int nt = 0; nt < 4; nt++) {
            const int n = n0 + warp_n * 32 + nt * 8 + 2 * tig;
            float bx = 0.0f, by = 0.0f;
            if (bias) { bx = bias[n]; by = bias[n + 1]; }
            const long mA = m0 + warp_m * 64 + mt * 16 + gid;
            float2 v0 = make_float2(acc[mt][nt][0] + bx, acc[mt][nt][1] + by);
            float2 v1 = make_float2(acc[mt][nt][2] + bx, acc[mt][nt][3] + by);
            *(float2*)(Cout + mA * CC + n)       = v0;
            *(float2*)(Cout + (mA + 8) * CC + n) = v1;
        }
    }
}

// ===========================================================================
// Causal flash attention (FFMA; q/k/v layout [tok][h*64+d]).
// grid = (T/64, H, B), block = 256.
// ===========================================================================
#define TILE_F (64 * 68)
#define ATTN_SMEM (4 * TILE_F * (int)sizeof(float))

__global__ __launch_bounds__(256) void attn_kernel(
    const float* __restrict__ Q, const float* __restrict__ K,
    const float* __restrict__ V, float* __restrict__ O)
{
    extern __shared__ __align__(16) float sm[];
    float* Qs = sm;
    float* Ks = sm + TILE_F;
    float* Vs = sm + 2 * TILE_F;
    float* Ps = sm + 3 * TILE_F;

    const int qb  = blockIdx.x;
    const int h   = blockIdx.y;
    const int b   = blockIdx.z;
    const int tid = threadIdx.x;
    const int tm0 = (tid >> 4) * 4;
    const int tn0 = (tid & 15) * 4;

    const long qrow = ((long)(b * TT + qb * 64)) * CC + h * DD;

    for (int idx = tid; idx < 64 * 64; idx += 256) {
        const int t = idx >> 6, d = idx & 63;
        Qs[d * 68 + t] = Q[qrow + (long)t * CC + d];
    }

    float m_i[4], l_i[4], acc[4][4];
#pragma unroll
    for (int i = 0; i < 4; i++) {
        m_i[i] = -1e30f; l_i[i] = 0.0f;
#pragma unroll
        for (int j = 0; j < 4; j++) acc[i][j] = 0.0f;
    }
    __syncthreads();

    for (int kb = 0; kb <= qb; kb++) {
        const long krow = ((long)(b * TT + kb * 64)) * CC + h * DD;
        for (int idx = tid; idx < 64 * 64; idx += 256) {
            const int j = idx >> 6, d = idx & 63;
            Ks[d * 68 + j] = K[krow + (long)j * CC + d];
            Vs[j * 68 + d] = V[krow + (long)j * CC + d];
        }
        __syncthreads();

        float sc[4][4];
#pragma unroll
        for (int i = 0; i < 4; i++)
#pragma unroll
            for (int j = 0; j < 4; j++) sc[i][j] = 0.0f;

#pragma unroll 8
        for (int d = 0; d < 64; d++) {
            const float4 qv = *(const float4*)(Qs + d * 68 + tm0);
            const float4 kv = *(const float4*)(Ks + d * 68 + tn0);
            const float q4[4] = {qv.x, qv.y, qv.z, qv.w};
            const float k4[4] = {kv.x, kv.y, kv.z, kv.w};
#pragma unroll
            for (int i = 0; i < 4; i++)
#pragma unroll
                for (int j = 0; j < 4; j++) sc[i][j] += q4[i] * k4[j];
        }

        const bool diag = (kb == qb);
        const float scale = 0.125f;

#pragma unroll
        for (int i = 0; i < 4; i++) {
            float rmax = -1e30f;
#pragma unroll
            for (int j = 0; j < 4; j++) {
                float sv = sc[i][j] * scale;
                if (diag && (tn0 + j) > (tm0 + i)) sv = -1e30f;
                sc[i][j] = sv;
                rmax = fmaxf(rmax, sv);
            }
            rmax = fmaxf(rmax, __shfl_xor_sync(0xffffffffu, rmax, 1));
            rmax = fmaxf(rmax, __shfl_xor_sync(0xffffffffu, rmax, 2));
            rmax = fmaxf(rmax, __shfl_xor_sync(0xffffffffu, rmax, 4));
            rmax = fmaxf(rmax, __shfl_xor_sync(0xffffffffu, rmax, 8));

            const float mnew = fmaxf(m_i[i], rmax);
            const float corr = __expf(m_i[i] - mnew);
            m_i[i] = mnew;

            float ls = 0.0f;
#pragma unroll
            for (int j = 0; j < 4; j++) {
                const float pv = __expf(sc[i][j] - mnew);
                sc[i][j] = pv;
                ls += pv;
            }
            ls += __shfl_xor_sync(0xffffffffu, ls, 1);
            ls += __shfl_xor_sync(0xffffffffu, ls, 2);
            ls += __shfl_xor_sync(0xffffffffu, ls, 4);
            ls += __shfl_xor_sync(0xffffffffu, ls, 8);

            l_i[i] = l_i[i] * corr + ls;
#pragma unroll
            for (int j = 0; j < 4; j++) acc[i][j] *= corr;
        }

#pragma unroll
        for (int j = 0; j < 4; j++)
#pragma unroll
            for (int i = 0; i < 4; i++)
                Ps[(tn0 + j) * 68 + tm0 + i] = sc[i][j];
        __syncthreads();

#pragma unroll 8
        for (int j = 0; j < 64; j++) {
            const float4 pv = *(const float4*)(Ps + j * 68 + tm0);
            const float4 vv = *(const float4*)(Vs + j * 68 + tn0);
            const float p4[4] = {pv.x, pv.y, pv.z, pv.w};
            const float v4[4] = {vv.x, vv.y, vv.z, vv.w};
#pragma unroll
            for (int i = 0; i < 4; i++)
#pragma unroll
                for (int jj = 0; jj < 4; jj++) acc[i][jj] += p4[i] * v4[jj];
        }
        __syncthreads();
    }

#pragma unroll
    for (int i = 0; i < 4; i++) {
        const float inv = 1.0f / l_i[i];
        const int t = qb * 64 + tm0 + i;
        float4 r = make_float4(acc[i][0] * inv, acc[i][1] * inv,
                               acc[i][2] * inv, acc[i][3] * inv);
        *(float4*)(O + ((long)(b * TT + t)) * CC + h * DD + tn0) = r;
    }
}

// ===========================================================================
extern "C" void kernel_launch(void* const* d_in, const int* in_sizes, int n_in,
                              void* d_out, int out_size)
{
    const float* x  = (const float*)d_in[0];
    const float* wq = (const float*)d_in[1];
    const float* wk = (const float*)d_in[2];
    const float* wv = (const float*)d_in[3];
    const float* wp = (const float*)d_in[4];
    const float* bp = (const float*)d_in[5];
    float* out = (float*)d_out;

    float *qp, *kp, *vp, *ap, *wqT, *wkT, *wvT, *wpT;
    cudaGetSymbolAddress((void**)&qp,  g_q);
    cudaGetSymbolAddress((void**)&kp,  g_k);
    cudaGetSymbolAddress((void**)&vp,  g_v);
    cudaGetSymbolAddress((void**)&ap,  g_attn);
    cudaGetSymbolAddress((void**)&wqT, g_wqT);
    cudaGetSymbolAddress((void**)&wkT, g_wkT);
    cudaGetSymbolAddress((void**)&wvT, g_wvT);
    cudaGetSymbolAddress((void**)&wpT, g_wpT);

    transpose_w<<<(CC * CC + 255) / 256, 256>>>(wq, wk, wv, wp, wqT, wkT, wvT, wpT);

    cudaFuncSetAttribute(gemm_mma,
                         cudaFuncAttributeMaxDynamicSharedMemorySize, GEMM_SMEM);
    dim3 gg(NTOK / 128, CC / 128);
    gemm_mma<<<gg, 256, GEMM_SMEM>>>(x, wqT, nullptr, qp);
    gemm_mma<<<gg, 256, GEMM_SMEM>>>(x, wkT, nullptr, kp);
    gemm_mma<<<gg, 256, GEMM_SMEM>>>(x, wvT, nullptr, vp);

    cudaFuncSetAttribute(attn_kernel,
                         cudaFuncAttributeMaxDynamicSharedMemorySize, ATTN_SMEM);
    attn_kernel<<<dim3(TT / 64, HH, BB), 256, ATTN_SMEM>>>(qp, kp, vp, ap);

    gemm_mma<<<gg, 256, GEMM_SMEM>>>(ap, wpT, bp, out);
}

// round 5
// speedup vs baseline: 2.8480x; 1.3502x over previous
#include <cuda_runtime.h>
#include <cstdint>

// Problem constants
#define BB 128
#define TT 256
#define CC 384
#define HH 6
#define DD 64
#define NTOK (BB * TT)   // 32768

// Scratch (static device globals — no dynamic allocation allowed)
__device__ float g_q[NTOK * CC];       // [b*T+t][h*64+d]
__device__ float g_k[NTOK * CC];
__device__ float g_v[NTOK * CC];
__device__ float g_attn[NTOK * CC];    // [b*T + t][h*D + d]
__device__ float g_wqT[CC * CC];       // [n=h*64+d][k=c]  K-major
__device__ float g_wkT[CC * CC];
__device__ float g_wvT[CC * CC];
__device__ float g_wpT[CC * CC];       // [n][k]

// ---------------------------------------------------------------------------
__device__ __forceinline__ float tf32r(float x) {
    uint32_t o;
    asm("cvt.rna.tf32.f32 %0, %1;" : "=r"(o) : "f"(x));
    return __uint_as_float(o);
}

__device__ __forceinline__ void mma_tf32(float* c, const uint32_t* a,
                                         const uint32_t* b) {
    asm volatile(
        "mma.sync.aligned.m16n8k8.row.col.f32.tf32.tf32.f32 "
        "{%0,%1,%2,%3}, {%4,%5,%6,%7}, {%8,%9}, {%0,%1,%2,%3};"
        : "+f"(c[0]), "+f"(c[1]), "+f"(c[2]), "+f"(c[3])
        : "r"(a[0]), "r"(a[1]), "r"(a[2]), "r"(a[3]), "r"(b[0]), "r"(b[1]));
}

// ===========================================================================
// Weight transpose: produce K-major B operands.
// ===========================================================================
__global__ void transpose_w(const float* __restrict__ wq, const float* __restrict__ wk,
                            const float* __restrict__ wv, const float* __restrict__ wp,
                            float* __restrict__ qT, float* __restrict__ kT,
                            float* __restrict__ vT, float* __restrict__ pT)
{
    int idx = blockIdx.x * 256 + threadIdx.x;
    if (idx >= CC * CC) return;
    int n = idx / CC, k = idx - n * CC;
    int h = n >> 6, d = n & 63;
    int src = (h * CC + k) * DD + d;
    qT[idx] = wq[src];
    kT[idx] = wk[src];
    vT[idx] = wv[src];
    pT[idx] = wp[k * CC + n];
}

// ===========================================================================
// Tensor-core tf32 GEMM core: C[m][n] = sum_k A[m][k]*Bt[n][k] (+bias)
//   CTA tile 128x128, warp tile 64x32, K-chunk 32, double-buffered SMEM.
// ===========================================================================
#define KTILE 32
#define NCHUNK (CC / KTILE)     // 12
#define SSTR 36
#define ASF (128 * SSTR)
#define GEMM_SMEM (4 * ASF * (int)sizeof(float))

__device__ __forceinline__ void gemm_core(
    const float* __restrict__ A, const float* __restrict__ Bt,
    const float* __restrict__ bias, float* __restrict__ Cout,
    int m0, int n0, float* sm)
{
    const int tid = threadIdx.x;
    const int wid = tid >> 5, lane = tid & 31;
    const int gid = lane >> 2, tig = lane & 3;
    const int warp_m = wid & 1;
    const int warp_n = wid >> 1;

    const int lr[4] = { (tid + 0) >> 3, (tid + 256) >> 3,
                        (tid + 512) >> 3, (tid + 768) >> 3 };
    const int lc = (tid & 7) * 4;

    float acc[4][4][4];
#pragma unroll
    for (int i = 0; i < 4; i++)
#pragma unroll
        for (int j = 0; j < 4; j++)
#pragma unroll
            for (int r = 0; r < 4; r++) acc[i][j][r] = 0.0f;

    float4 ra[4], rb[4];
#pragma unroll
    for (int i = 0; i < 4; i++) {
        ra[i] = *(const float4*)(A  + (long)(m0 + lr[i]) * CC + lc);
        rb[i] = *(const float4*)(Bt + (long)(n0 + lr[i]) * CC + lc);
    }
#pragma unroll
    for (int i = 0; i < 4; i++) {
        float* as = sm + 0 * ASF + lr[i] * SSTR + lc;
        float* bs = sm + 2 * ASF + lr[i] * SSTR + lc;
        as[0] = tf32r(ra[i].x); as[1] = tf32r(ra[i].y);
        as[2] = tf32r(ra[i].z); as[3] = tf32r(ra[i].w);
        bs[0] = tf32r(rb[i].x); bs[1] = tf32r(rb[i].y);
        bs[2] = tf32r(rb[i].z); bs[3] = tf32r(rb[i].w);
    }
    __syncthreads();

    for (int c = 0; c < NCHUNK; c++) {
        const int s = c & 1;
        const bool more = (c + 1 < NCHUNK);
        if (more) {
            const int k0 = (c + 1) * KTILE;
#pragma unroll
            for (int i = 0; i < 4; i++) {
                ra[i] = *(const float4*)(A  + (long)(m0 + lr[i]) * CC + k0 + lc);
                rb[i] = *(const float4*)(Bt + (long)(n0 + lr[i]) * CC + k0 + lc);
            }
        }

        const uint32_t* Au = (const uint32_t*)(sm + s * ASF);
        const uint32_t* Bu = (const uint32_t*)(sm + (2 + s) * ASF);

#pragma unroll
        for (int ks = 0; ks < 4; ks++) {
            uint32_t af[4][4], bf[4][2];
#pragma unroll
            for (int mt = 0; mt < 4; mt++) {
                const int row = warp_m * 64 + mt * 16 + gid;
                const int col = ks * 8 + tig;
                af[mt][0] = Au[row * SSTR + col];
                af[mt][1] = Au[(row + 8) * SSTR + col];
                af[mt][2] = Au[row * SSTR + col + 4];
                af[mt][3] = Au[(row + 8) * SSTR + col + 4];
            }
#pragma unroll
            for (int nt = 0; nt < 4; nt++) {
                const int row = warp_n * 32 + nt * 8 + gid;
                const int col = ks * 8 + tig;
                bf[nt][0] = Bu[row * SSTR + col];
                bf[nt][1] = Bu[row * SSTR + col + 4];
            }
#pragma unroll
            for (int mt = 0; mt < 4; mt++)
#pragma unroll
                for (int nt = 0; nt < 4; nt++)
                    mma_tf32(acc[mt][nt], af[mt], bf[nt]);
        }

        if (more) {
            const int so = s ^ 1;
#pragma unroll
            for (int i = 0; i < 4; i++) {
                float* as = sm + so * ASF + lr[i] * SSTR + lc;
                float* bs = sm + (2 + so) * ASF + lr[i] * SSTR + lc;
                as[0] = tf32r(ra[i].x); as[1] = tf32r(ra[i].y);
                as[2] = tf32r(ra[i].z); as[3] = tf32r(ra[i].w);
                bs[0] = tf32r(rb[i].x); bs[1] = tf32r(rb[i].y);
                bs[2] = tf32r(rb[i].z); bs[3] = tf32r(rb[i].w);
            }
            __syncthreads();
        }
    }

#pragma unroll
    for (int mt = 0; mt < 4; mt++) {
#pragma unroll
        for (int nt = 0; nt < 4; nt++) {
            const int n = n0 + warp_n * 32 + nt * 8 + 2 * tig;
            float bx = 0.0f, by = 0.0f;
            if (bias) { bx = bias[n]; by = bias[n + 1]; }
            const long mA = m0 + warp_m * 64 + mt * 16 + gid;
            float2 v0 = make_float2(acc[mt][nt][0] + bx, acc[mt][nt][1] + by);
            float2 v1 = make_float2(acc[mt][nt][2] + bx, acc[mt][nt][3] + by);
            *(float2*)(Cout + mA * CC + n)       = v0;
            *(float2*)(Cout + (mA + 8) * CC + n) = v1;
        }
    }
}

// Output-projection GEMM (single B matrix, with bias)
__global__ __launch_bounds__(256) void gemm_mma(
    const float* __restrict__ A, const float* __restrict__ Bt,
    const float* __restrict__ bias, float* __restrict__ Cout)
{
    extern __shared__ __align__(16) float sm[];
    gemm_core(A, Bt, bias, Cout, blockIdx.x * 128, blockIdx.y * 128, sm);
}

// Fused QKV GEMM: grid.y in [0,9): matrix = y/3, n0 = (y%3)*128
__global__ __launch_bounds__(256) void gemm_qkv(
    const float* __restrict__ X,
    const float* __restrict__ wqT, const float* __restrict__ wkT,
    const float* __restrict__ wvT,
    float* __restrict__ qO, float* __restrict__ kO, float* __restrict__ vO)
{
    extern __shared__ __align__(16) float sm[];
    const int mat = blockIdx.y / 3;
    const int n0  = (blockIdx.y % 3) * 128;
    const float* Bt = (mat == 0) ? wqT : (mat == 1) ? wkT : wvT;
    float* Cout     = (mat == 0) ? qO  : (mat == 1) ? kO  : vO;
    gemm_core(X, Bt, nullptr, Cout, blockIdx.x * 128, n0, sm);
}

// ===========================================================================
// Tensor-core causal flash attention.
//   grid = (T/64, H, B), block = 128 (4 warps, 16 query rows each).
//   SMEM: Qs[q][d], Ks[key][d], Vt[d][key], Ps[q][key], stride 68.
// ===========================================================================
#define ASTR 68
#define ATILE (64 * ASTR)
#define ATTN_SMEM (4 * ATILE * (int)sizeof(float))

__global__ __launch_bounds__(128) void attn_mma(
    const float* __restrict__ Q, const float* __restrict__ K,
    const float* __restrict__ V, float* __restrict__ O)
{
    extern __shared__ __align__(16) float sm[];
    float* Qs = sm;
    float* Ks = sm + ATILE;
    float* Vt = sm + 2 * ATILE;
    float* Ps = sm + 3 * ATILE;

    const int qb  = blockIdx.x;
    const int h   = blockIdx.y;
    const int b   = blockIdx.z;
    const int tid = threadIdx.x;
    const int wid = tid >> 5, lane = tid & 31;
    const int gid = lane >> 2, tig = lane & 3;
    const int mrow = wid * 16 + gid;       // warp-local query row (and +8)

    const long qbase = ((long)(b * TT + qb * 64)) * CC + h * DD;

    // Load Q (tf32-rounded), row-major [q][d]
#pragma unroll
    for (int it = 0; it < 8; it++) {
        const int f = it * 128 + tid;          // 64 rows x 16 float4
        const int r = f >> 4, d = (f & 15) * 4;
        float4 v = *(const float4*)(Q + qbase + (long)r * CC + d);
        float* qs = Qs + r * ASTR + d;
        qs[0] = tf32r(v.x); qs[1] = tf32r(v.y);
        qs[2] = tf32r(v.z); qs[3] = tf32r(v.w);
    }

    float o[8][4];
#pragma unroll
    for (int nt = 0; nt < 8; nt++)
#pragma unroll
        for (int r = 0; r < 4; r++) o[nt][r] = 0.0f;
    float m0 = -1e30f, m8 = -1e30f, l0 = 0.0f, l8 = 0.0f;

    __syncthreads();

    for (int kb = 0; kb <= qb; kb++) {
        const long kbase = ((long)(b * TT + kb * 64)) * CC + h * DD;

        // Load K row-major, V transposed [d][key]
#pragma unroll
        for (int it = 0; it < 8; it++) {
            const int f = it * 128 + tid;
            const int r = f >> 4, d = (f & 15) * 4;
            float4 kv = *(const float4*)(K + kbase + (long)r * CC + d);
            float* ks = Ks + r * ASTR + d;
            ks[0] = tf32r(kv.x); ks[1] = tf32r(kv.y);
            ks[2] = tf32r(kv.z); ks[3] = tf32r(kv.w);
            float4 vv = *(const float4*)(V + kbase + (long)r * CC + d);
            Vt[(d + 0) * ASTR + r] = tf32r(vv.x);
            Vt[(d + 1) * ASTR + r] = tf32r(vv.y);
            Vt[(d + 2) * ASTR + r] = tf32r(vv.z);
            Vt[(d + 3) * ASTR + r] = tf32r(vv.w);
        }
        __syncthreads();

        // S = Q K^T : M=16 (warp rows), N=64 (8 n-tiles), K=64 (8 k-steps)
        float s[8][4];
#pragma unroll
        for (int nt = 0; nt < 8; nt++)
#pragma unroll
            for (int r = 0; r < 4; r++) s[nt][r] = 0.0f;

        const uint32_t* Qu = (const uint32_t*)Qs;
        const uint32_t* Ku = (const uint32_t*)Ks;
#pragma unroll
        for (int ks = 0; ks < 8; ks++) {
            uint32_t af[4];
            const int col = ks * 8 + tig;
            af[0] = Qu[mrow * ASTR + col];
            af[1] = Qu[(mrow + 8) * ASTR + col];
            af[2] = Qu[mrow * ASTR + col + 4];
            af[3] = Qu[(mrow + 8) * ASTR + col + 4];
#pragma unroll
            for (int nt = 0; nt < 8; nt++) {
                uint32_t bf[2];
                bf[0] = Ku[(nt * 8 + gid) * ASTR + col];
                bf[1] = Ku[(nt * 8 + gid) * ASTR + col + 4];
                mma_tf32(s[nt], af, bf);
            }
        }

        // Scale + causal mask + online softmax
        const bool diag = (kb == qb);
        const float scale = 0.125f;
        float rmax0 = -1e30f, rmax8 = -1e30f;
#pragma unroll
        for (int nt = 0; nt < 8; nt++) {
            const int c0 = nt * 8 + 2 * tig;
#pragma unroll
            for (int r = 0; r < 4; r++) {
                const int col = c0 + (r & 1);
                const int row = mrow + ((r >> 1) << 3);
                float v = s[nt][r] * scale;
                if (diag && col > row) v = -1e30f;
                s[nt][r] = v;
                if (r < 2) rmax0 = fmaxf(rmax0, v);
                else       rmax8 = fmaxf(rmax8, v);
            }
        }
        rmax0 = fmaxf(rmax0, __shfl_xor_sync(0xffffffffu, rmax0, 1));
        rmax0 = fmaxf(rmax0, __shfl_xor_sync(0xffffffffu, rmax0, 2));
        rmax8 = fmaxf(rmax8, __shfl_xor_sync(0xffffffffu, rmax8, 1));
        rmax8 = fmaxf(rmax8, __shfl_xor_sync(0xffffffffu, rmax8, 2));

        const float mn0 = fmaxf(m0, rmax0);
        const float mn8 = fmaxf(m8, rmax8);
        const float corr0 = __expf(m0 - mn0);
        const float corr8 = __expf(m8 - mn8);
        m0 = mn0; m8 = mn8;

        float ls0 = 0.0f, ls8 = 0.0f;
#pragma unroll
        for (int nt = 0; nt < 8; nt++) {
            float p0 = __expf(s[nt][0] - mn0);
            float p1 = __expf(s[nt][1] - mn0);
            float p2 = __expf(s[nt][2] - mn8);
            float p3 = __expf(s[nt][3] - mn8);
            s[nt][0] = p0; s[nt][1] = p1; s[nt][2] = p2; s[nt][3] = p3;
            ls0 += p0 + p1;
            ls8 += p2 + p3;
        }
        ls0 += __shfl_xor_sync(0xffffffffu, ls0, 1);
        ls0 += __shfl_xor_sync(0xffffffffu, ls0, 2);
        ls8 += __shfl_xor_sync(0xffffffffu, ls8, 1);
        ls8 += __shfl_xor_sync(0xffffffffu, ls8, 2);

        l0 = l0 * corr0 + ls0;
        l8 = l8 * corr8 + ls8;
#pragma unroll
        for (int nt = 0; nt < 8; nt++) {
            o[nt][0] *= corr0; o[nt][1] *= corr0;
            o[nt][2] *= corr8; o[nt][3] *= corr8;
        }

        // Write P (tf32) to SMEM for fragment reload
#pragma unroll
        for (int nt = 0; nt < 8; nt++) {
            float* p0 = Ps + mrow * ASTR + nt * 8 + 2 * tig;
            p0[0]            = tf32r(s[nt][0]);
            p0[1]            = tf32r(s[nt][1]);
            p0[8 * ASTR + 0] = tf32r(s[nt][2]);
            p0[8 * ASTR + 1] = tf32r(s[nt][3]);
        }
        __syncwarp();

        // O += P @ V : A = Ps rows, B = Vt[dim][key]
        const uint32_t* Pu = (const uint32_t*)Ps;
        const uint32_t* Vu = (const uint32_t*)Vt;
#pragma unroll
        for (int ks = 0; ks < 8; ks++) {
            uint32_t af[4];
            const int col = ks * 8 + tig;
            af[0] = Pu[mrow * ASTR + col];
            af[1] = Pu[(mrow + 8) * ASTR + col];
            af[2] = Pu[mrow * ASTR + col + 4];
            af[3] = Pu[(mrow + 8) * ASTR + col + 4];
#pragma unroll
            for (int nt = 0; nt < 8; nt++) {
                uint32_t bf[2];
                bf[0] = Vu[(nt * 8 + gid) * ASTR + col];
                bf[1] = Vu[(nt * 8 + gid) * ASTR + col + 4];
                mma_tf32(o[nt], af, bf);
            }
        }
        __syncthreads();   // protect Ks/Vt before next iteration's load
    }

    // Epilogue
    const float inv0 = 1.0f / l0;
    const float inv8 = 1.0f / l8;
    const long orow0 = (long)(b * TT + qb * 64 + mrow) * CC + h * DD;
#pragma unroll
    for (int nt = 0; nt < 8; nt++) {
        const int col = nt * 8 + 2 * tig;
        *(float2*)(O + orow0 + col) =
            make_float2(o[nt][0] * inv0, o[nt][1] * inv0);
        *(float2*)(O + orow0 + 8 * CC + col) =
            make_float2(o[nt][2] * inv8, o[nt][3] * inv8);
    }
}

// ===========================================================================
extern "C" void kernel_launch(void* const* d_in, const int* in_sizes, int n_in,
                              void* d_out, int out_size)
{
    const float* x  = (const float*)d_in[0];
    const float* wq = (const float*)d_in[1];
    const float* wk = (const float*)d_in[2];
    const float* wv = (const float*)d_in[3];
    const float* wp = (const float*)d_in[4];
    const float* bp = (const float*)d_in[5];
    float* out = (float*)d_out;

    float *qp, *kp, *vp, *ap, *wqT, *wkT, *wvT, *wpT;
    cudaGetSymbolAddress((void**)&qp,  g_q);
    cudaGetSymbolAddress((void**)&kp,  g_k);
    cudaGetSymbolAddress((void**)&vp,  g_v);
    cudaGetSymbolAddress((void**)&ap,  g_attn);
    cudaGetSymbolAddress((void**)&wqT, g_wqT);
    cudaGetSymbolAddress((void**)&wkT, g_wkT);
    cudaGetSymbolAddress((void**)&wvT, g_wvT);
    cudaGetSymbolAddress((void**)&wpT, g_wpT);

    transpose_w<<<(CC * CC + 255) / 256, 256>>>(wq, wk, wv, wp, wqT, wkT, wvT, wpT);

    cudaFuncSetAttribute(gemm_qkv,
                         cudaFuncAttributeMaxDynamicSharedMemorySize, GEMM_SMEM);
    cudaFuncSetAttribute(gemm_mma,
                         cudaFuncAttributeMaxDynamicSharedMemorySize, GEMM_SMEM);
    gemm_qkv<<<dim3(NTOK / 128, 9), 256, GEMM_SMEM>>>(x, wqT, wkT, wvT, qp, kp, vp);

    cudaFuncSetAttribute(attn_mma,
                         cudaFuncAttributeMaxDynamicSharedMemorySize, ATTN_SMEM);
    attn_mma<<<dim3(TT / 64, HH, BB), 128, ATTN_SMEM>>>(qp, kp, vp, ap);

    gemm_mma<<<dim3(NTOK / 128, CC / 128), 256, GEMM_SMEM>>>(ap, wpT, bp, out);
}